// round 1
// baseline (speedup 1.0000x reference)
#include <cuda_runtime.h>
#include <math.h>

#define N_TOK 32768
#define M_CODE 4096
#define D_DIM 256

#define TM 128
#define TN 128
#define TK 16

// Scratch (no allocations allowed in kernel_launch)
__device__ float g_e2[M_CODE];
__device__ int   g_counts[M_CODE];
__device__ float g_loss_sum;

// ---------------------------------------------------------------------------
// Zero the per-launch accumulators (graph replays must be deterministic).
// ---------------------------------------------------------------------------
__global__ void vq_init_kernel() {
    int t = blockIdx.x * blockDim.x + threadIdx.x;
    if (t < M_CODE) g_counts[t] = 0;
    if (t == 0) g_loss_sum = 0.0f;
}

// ---------------------------------------------------------------------------
// e2[m] = ||embed[m]||^2
// ---------------------------------------------------------------------------
__global__ void vq_e2_kernel(const float* __restrict__ embed) {
    int m = blockIdx.x * blockDim.x + threadIdx.x;
    if (m >= M_CODE) return;
    const float4* row = reinterpret_cast<const float4*>(embed + (size_t)m * D_DIM);
    float s = 0.0f;
#pragma unroll
    for (int i = 0; i < D_DIM / 4; i++) {
        float4 v = row[i];
        s += v.x * v.x + v.y * v.y + v.z * v.z + v.w * v.w;
    }
    g_e2[m] = s;
}

// ---------------------------------------------------------------------------
// Main fused GEMM + argmin + gather + loss-partial + histogram kernel.
// Block: 256 threads, tile TM=128 tokens x TN=128 codes, 8x8 micro-tile/thread.
// Thread layout: tx = tid & 15 (code dim), ty = tid >> 4 (token dim),
// interleaved mapping: row = ty + 16*r, col = tx + 16*c  (broadcast-friendly LDS).
// ---------------------------------------------------------------------------
__global__ __launch_bounds__(256, 2)
void vq_main_kernel(const float* __restrict__ x,
                    const float* __restrict__ embed,
                    float* __restrict__ quant_out,
                    float* __restrict__ idx_out) {
    __shared__ float xs[TK][TM];
    __shared__ float es[TK][TN];

    const int tid = threadIdx.x;
    const int tx = tid & 15;
    const int ty = tid >> 4;
    const int row0 = blockIdx.x * TM;

    float bestv[8];
    int   besti[8];
#pragma unroll
    for (int r = 0; r < 8; r++) { bestv[r] = 3.4e38f; besti[r] = 0; }

    for (int ct = 0; ct < M_CODE / TN; ct++) {
        const int col0 = ct * TN;

        float acc[8][8];
#pragma unroll
        for (int r = 0; r < 8; r++)
#pragma unroll
            for (int c = 0; c < 8; c++) acc[r][c] = 0.0f;

        for (int kt = 0; kt < D_DIM / TK; kt++) {
            // ---- load x tile: TM x TK floats, transposed into xs[k][row] ----
#pragma unroll
            for (int q = tid; q < (TM * TK) / 4; q += 256) {
                int row = q >> 2;           // 4 float4 per row of 16 k
                int kq = (q & 3) << 2;      // k offset 0,4,8,12
                float4 v = *reinterpret_cast<const float4*>(
                    x + (size_t)(row0 + row) * D_DIM + kt * TK + kq);
                xs[kq + 0][row] = v.x;
                xs[kq + 1][row] = v.y;
                xs[kq + 2][row] = v.z;
                xs[kq + 3][row] = v.w;
            }
            // ---- load embed tile: TN x TK floats, transposed into es[k][col] ----
#pragma unroll
            for (int q = tid; q < (TN * TK) / 4; q += 256) {
                int col = q >> 2;
                int kq = (q & 3) << 2;
                float4 v = *reinterpret_cast<const float4*>(
                    embed + (size_t)(col0 + col) * D_DIM + kt * TK + kq);
                es[kq + 0][col] = v.x;
                es[kq + 1][col] = v.y;
                es[kq + 2][col] = v.z;
                es[kq + 3][col] = v.w;
            }
            __syncthreads();

#pragma unroll
            for (int k = 0; k < TK; k++) {
                float a[8], b[8];
#pragma unroll
                for (int r = 0; r < 8; r++) a[r] = xs[k][ty + 16 * r];
#pragma unroll
                for (int c = 0; c < 8; c++) b[c] = es[k][tx + 16 * c];
#pragma unroll
                for (int r = 0; r < 8; r++)
#pragma unroll
                    for (int c = 0; c < 8; c++)
                        acc[r][c] += a[r] * b[c];
            }
            __syncthreads();
        }

        // ---- per-tile score + running per-thread argmin ----
#pragma unroll
        for (int c = 0; c < 8; c++) {
            int col = col0 + tx + 16 * c;
            float e2v = g_e2[col];
#pragma unroll
            for (int r = 0; r < 8; r++) {
                float s = fmaf(-2.0f, acc[r][c], e2v);
                if (s < bestv[r] || (s == bestv[r] && col < besti[r])) {
                    bestv[r] = s;
                    besti[r] = col;
                }
            }
        }
    }

    // ---- reduce argmin across the 16 tx threads per token row ----
    __shared__ float redv[TM][16];
    __shared__ int   redi[TM][16];
    __shared__ int   final_idx[TM];
#pragma unroll
    for (int r = 0; r < 8; r++) {
        redv[ty + 16 * r][tx] = bestv[r];
        redi[ty + 16 * r][tx] = besti[r];
    }
    __syncthreads();

    if (tid < TM) {
        float bv = 3.4e38f;
        int bi = M_CODE;
#pragma unroll
        for (int j = 0; j < 16; j++) {
            float v = redv[tid][j];
            int i = redi[tid][j];
            if (v < bv || (v == bv && i < bi)) { bv = v; bi = i; }
        }
        final_idx[tid] = bi;
        idx_out[row0 + tid] = (float)bi;
        atomicAdd(&g_counts[bi], 1);
    }
    __syncthreads();

    // ---- gather quantized rows, accumulate loss partial ----
    float lsum = 0.0f;
    for (int e = tid; e < TM * D_DIM; e += 256) {
        int r = e >> 8;          // D_DIM = 256
        int k = e & 255;
        float q = embed[(size_t)final_idx[r] * D_DIM + k];
        float xv = x[(size_t)(row0 + r) * D_DIM + k];
        quant_out[(size_t)(row0 + r) * D_DIM + k] = q;
        float d = q - xv;
        lsum += d * d;
    }

    __shared__ float lred[256];
    lred[tid] = lsum;
    __syncthreads();
#pragma unroll
    for (int s = 128; s > 0; s >>= 1) {
        if (tid < s) lred[tid] += lred[tid + s];
        __syncthreads();
    }
    if (tid == 0) atomicAdd(&g_loss_sum, lred[0]);
}

// ---------------------------------------------------------------------------
// Finalize: loss scalar + perplexity from histogram.
// ---------------------------------------------------------------------------
__global__ void vq_finalize_kernel(float* __restrict__ loss_out,
                                   float* __restrict__ perp_out) {
    __shared__ float hred[256];
    int tid = threadIdx.x;
    float h = 0.0f;
    for (int m = tid; m < M_CODE; m += 256) {
        float p = (float)g_counts[m] * (1.0f / (float)N_TOK);
        h += p * logf(p + 1e-10f);
    }
    hred[tid] = h;
    __syncthreads();
#pragma unroll
    for (int s = 128; s > 0; s >>= 1) {
        if (tid < s) hred[tid] += hred[tid + s];
        __syncthreads();
    }
    if (tid == 0) {
        // loss = 0.25*mean((q-x)^2) + 1.0*mean((q-x)^2) = 1.25 * sum / (N*D)
        *loss_out = 1.25f * g_loss_sum / (float)((size_t)N_TOK * D_DIM);
        *perp_out = expf(-hred[0]);
    }
}

// ---------------------------------------------------------------------------
extern "C" void kernel_launch(void* const* d_in, const int* in_sizes, int n_in,
                              void* d_out, int out_size) {
    const float* x = (const float*)d_in[0];      // [N, D]
    const float* embed = (const float*)d_in[1];  // [M, D]

    float* out = (float*)d_out;
    float* quant = out;                                   // N*D
    float* idxp  = out + (size_t)N_TOK * D_DIM;           // N
    float* lossp = idxp + N_TOK;                          // 1
    float* perpp = lossp + 1;                             // 1

    vq_init_kernel<<<(M_CODE + 255) / 256, 256>>>();
    vq_e2_kernel<<<(M_CODE + 255) / 256, 256>>>(embed);
    vq_main_kernel<<<N_TOK / TM, 256>>>(x, embed, quant, idxp);
    vq_finalize_kernel<<<1, 256>>>(lossp, perpp);
}

// round 4
// speedup vs baseline: 2.7696x; 2.7696x over previous
#include <cuda_runtime.h>
#include <cuda_fp16.h>
#include <math.h>
#include <stdint.h>

#define N_TOK 32768
#define M_CODE 4096
#define D_DIM 256
#define NT 256                        // codes per tile
#define CT_COUNT (M_CODE / NT)        // 16
#define CHUNKS (CT_COUNT * 8)         // 128 chunks of 32 k

// ---------------- smem layout (bytes) ----------------
#define A_PITCH 264                    // halves per row (256 + 8 pad)
#define A_SPLIT 67584                  // 128 * 264 * 2
#define SM_A    0                      // [2 splits][128 rows][264 halves]
#define SM_B    135168
#define B_BUF   40960                  // per double-buffer
#define B_SPLIT 20480                  // per split within buffer
#define B_PITCH 40                     // halves per row (32 + 8 pad)
#define SM_E2   217088                 // 256 floats
#define SM_FIDX 218112                 // 128 ints
#define SMEM_TOTAL 218624

__device__ float g_e2[M_CODE];
__device__ int   g_counts[M_CODE];
__device__ float g_loss_sum;
__device__ __align__(16) __half g_eh[M_CODE * D_DIM];
__device__ __align__(16) __half g_el[M_CODE * D_DIM];

// ---------------------------- helpers ----------------------------------
__device__ __forceinline__ uint32_t smem_u32(const void* p) {
    uint32_t a;
    asm("{ .reg .u64 t; cvta.to.shared.u64 t, %1; cvt.u32.u64 %0, t; }"
        : "=r"(a) : "l"(p));
    return a;
}
__device__ __forceinline__ uint32_t lds32(uint32_t a) {
    uint32_t v;
    asm volatile("ld.shared.b32 %0, [%1];" : "=r"(v) : "r"(a));
    return v;
}
__device__ __forceinline__ void cp16(uint32_t dst, const void* src) {
    asm volatile("cp.async.cg.shared.global [%0], [%1], 16;"
                 :: "r"(dst), "l"(src) : "memory");
}
__device__ __forceinline__ void cp_commit() {
    asm volatile("cp.async.commit_group;" ::: "memory");
}
__device__ __forceinline__ void cp_wait1() {
    asm volatile("cp.async.wait_group 1;" ::: "memory");
}
__device__ __forceinline__ void mma16816(float* c, const uint32_t* a, const uint32_t* b) {
    asm volatile(
        "mma.sync.aligned.m16n8k16.row.col.f32.f16.f16.f32 "
        "{%0,%1,%2,%3}, {%4,%5,%6,%7}, {%8,%9}, {%0,%1,%2,%3};"
        : "+f"(c[0]), "+f"(c[1]), "+f"(c[2]), "+f"(c[3])
        : "r"(a[0]), "r"(a[1]), "r"(a[2]), "r"(a[3]), "r"(b[0]), "r"(b[1]));
}

// ----------------------------- small kernels --------------------------------
__global__ void vq_init_kernel() {
    int t = blockIdx.x * blockDim.x + threadIdx.x;
    if (t < M_CODE) g_counts[t] = 0;
    if (t == 0) g_loss_sum = 0.0f;
}
__global__ void vq_e2_kernel(const float* __restrict__ embed) {
    int m = blockIdx.x * blockDim.x + threadIdx.x;
    if (m >= M_CODE) return;
    const float4* row = reinterpret_cast<const float4*>(embed + (size_t)m * D_DIM);
    float s = 0.0f;
#pragma unroll
    for (int i = 0; i < D_DIM / 4; i++) {
        float4 v = row[i];
        s += v.x * v.x + v.y * v.y + v.z * v.z + v.w * v.w;
    }
    g_e2[m] = s;
}
// split embed into fp16 hi/lo
__global__ void vq_split_kernel(const float* __restrict__ embed) {
    int i = blockIdx.x * blockDim.x + threadIdx.x;   // one float4 each
    if (i >= M_CODE * D_DIM / 4) return;
    float4 v = reinterpret_cast<const float4*>(embed)[i];
    __half hx = __float2half_rn(v.x), hy = __float2half_rn(v.y);
    __half hz = __float2half_rn(v.z), hw = __float2half_rn(v.w);
    __half lx = __float2half_rn(v.x - __half2float(hx));
    __half ly = __float2half_rn(v.y - __half2float(hy));
    __half lz = __float2half_rn(v.z - __half2float(hz));
    __half lw = __float2half_rn(v.w - __half2float(hw));
    half2* ph = reinterpret_cast<half2*>(g_eh);
    half2* pl = reinterpret_cast<half2*>(g_el);
    ph[i * 2 + 0] = __halves2half2(hx, hy);
    ph[i * 2 + 1] = __halves2half2(hz, hw);
    pl[i * 2 + 0] = __halves2half2(lx, ly);
    pl[i * 2 + 1] = __halves2half2(lz, lw);
}

// ------------------------------ main kernel ---------------------------------
__global__ __launch_bounds__(256, 1)
void vq_main_kernel(const float* __restrict__ x,
                    const float* __restrict__ embed,
                    float* __restrict__ quant_out,
                    float* __restrict__ idx_out) {
    extern __shared__ char smem[];
    const uint32_t sb = smem_u32(smem);
    const int tid = threadIdx.x;
    const int lane = tid & 31;
    const int wid = tid >> 5;
    const int wm = wid >> 2;        // 0..1 (m block of 64 rows)
    const int wn = wid & 3;         // 0..3 (n block of 64 cols)
    const int row0 = blockIdx.x * 128;

    float* e2s = (float*)(smem + SM_E2);
    int* fidx = (int*)(smem + SM_FIDX);

    // ---- stage x: split to fp16 hi/lo into smem [-2*x] ----
    for (int i = tid; i < 128 * 64; i += 256) {     // 8192 float4
        int row = i >> 6;
        int kq = (i & 63) << 2;
        float4 v = *(const float4*)(x + (size_t)(row0 + row) * D_DIM + kq);
        float ax = -2.0f * v.x, ay = -2.0f * v.y, az = -2.0f * v.z, aw = -2.0f * v.w;
        __half hx = __float2half_rn(ax), hy = __float2half_rn(ay);
        __half hz = __float2half_rn(az), hw = __float2half_rn(aw);
        __half lx = __float2half_rn(ax - __half2float(hx));
        __half ly = __float2half_rn(ay - __half2float(hy));
        __half lz = __float2half_rn(az - __half2float(hz));
        __half lw = __float2half_rn(aw - __half2float(hw));
        half2* dh = (half2*)(smem + SM_A + (size_t)(row * A_PITCH + kq) * 2);
        half2* dl = (half2*)(smem + SM_A + A_SPLIT + (size_t)(row * A_PITCH + kq) * 2);
        dh[0] = __halves2half2(hx, hy);
        dh[1] = __halves2half2(hz, hw);
        dl[0] = __halves2half2(lx, ly);
        dl[1] = __halves2half2(lz, lw);
    }

    // ---- prologue: async-load B chunk 0 ----
    {
        const __half* srcs[2] = {g_eh, g_el};
#pragma unroll
        for (int s = 0; s < 2; s++) {
            const __half* src = srcs[s] + (size_t)tid * D_DIM;   // ct=0,kc=0
            uint32_t dst = sb + SM_B + s * B_SPLIT + tid * (B_PITCH * 2);
#pragma unroll
            for (int j = 0; j < 4; j++) cp16(dst + j * 16, src + j * 8);
        }
        cp_commit();
    }

    float acc[4][8][4];
    float bv[8];
    int bi[8];
#pragma unroll
    for (int s = 0; s < 8; s++) { bv[s] = 3.4e38f; bi[s] = 0; }

    for (int c = 0; c < CHUNKS; c++) {
        const int ct = c >> 3, kc = c & 7, buf = c & 1;

        // RACE FIX: the prefetch below writes buffer (c+1)&1, which lagging
        // warps may still be reading from iteration c-1's compute. Barrier
        // separates those reads from the new cp.async writes.
        if (c) __syncthreads();

        // prefetch chunk c+1
        if (c + 1 < CHUNKS) {
            const int nct = (c + 1) >> 3, nkc = (c + 1) & 7, nbuf = (c + 1) & 1;
            const __half* srcs[2] = {g_eh, g_el};
#pragma unroll
            for (int s = 0; s < 2; s++) {
                const __half* src = srcs[s] + (size_t)(nct * NT + tid) * D_DIM + nkc * 32;
                uint32_t dst = sb + SM_B + nbuf * B_BUF + s * B_SPLIT + tid * (B_PITCH * 2);
#pragma unroll
                for (int j = 0; j < 4; j++) cp16(dst + j * 16, src + j * 8);
            }
        }
        cp_commit();
        cp_wait1();
        __syncthreads();

        if (kc == 0) {
#pragma unroll
            for (int mt = 0; mt < 4; mt++)
#pragma unroll
                for (int nt = 0; nt < 8; nt++)
#pragma unroll
                    for (int q = 0; q < 4; q++) acc[mt][nt][q] = 0.0f;
            e2s[tid] = g_e2[ct * NT + tid];
        }

        // ---- compute: 2 k-steps of 16 ----
#pragma unroll
        for (int ks = 0; ks < 2; ks++) {
            const int kk = kc * 32 + ks * 16 + (lane & 3) * 2;   // global k for A
            const int kl = ks * 16 + (lane & 3) * 2;             // chunk-local k for B

            uint32_t a[2][4][4];
#pragma unroll
            for (int s = 0; s < 2; s++)
#pragma unroll
                for (int mt = 0; mt < 4; mt++) {
                    int ar = wm * 64 + mt * 16 + (lane >> 2);
                    uint32_t base = sb + SM_A + s * A_SPLIT + (ar * A_PITCH + kk) * 2;
                    a[s][mt][0] = lds32(base);
                    a[s][mt][1] = lds32(base + 8 * A_PITCH * 2);
                    a[s][mt][2] = lds32(base + 16);
                    a[s][mt][3] = lds32(base + 8 * A_PITCH * 2 + 16);
                }

            uint32_t b[8][2];
            // --- pass hh + lh with B_hi ---
#pragma unroll
            for (int nt = 0; nt < 8; nt++) {
                int n = wn * 64 + nt * 8 + (lane >> 2);
                uint32_t base = sb + SM_B + buf * B_BUF + 0 * B_SPLIT + (n * B_PITCH + kl) * 2;
                b[nt][0] = lds32(base);
                b[nt][1] = lds32(base + 16);
            }
#pragma unroll
            for (int mt = 0; mt < 4; mt++)
#pragma unroll
                for (int nt = 0; nt < 8; nt++) {
                    mma16816(acc[mt][nt], a[0][mt], b[nt]);
                    mma16816(acc[mt][nt], a[1][mt], b[nt]);
                }
            // --- pass hl with B_lo ---
#pragma unroll
            for (int nt = 0; nt < 8; nt++) {
                int n = wn * 64 + nt * 8 + (lane >> 2);
                uint32_t base = sb + SM_B + buf * B_BUF + 1 * B_SPLIT + (n * B_PITCH + kl) * 2;
                b[nt][0] = lds32(base);
                b[nt][1] = lds32(base + 16);
            }
#pragma unroll
            for (int mt = 0; mt < 4; mt++)
#pragma unroll
                for (int nt = 0; nt < 8; nt++)
                    mma16816(acc[mt][nt], a[0][mt], b[nt]);
        }

        // ---- epilogue of this code tile: fold e2, running argmin ----
        if (kc == 7) {
#pragma unroll
            for (int mt = 0; mt < 4; mt++)
#pragma unroll
                for (int h = 0; h < 2; h++) {
                    int slot = mt * 2 + h;
#pragma unroll
                    for (int nt = 0; nt < 8; nt++)
#pragma unroll
                        for (int q = 0; q < 2; q++) {
                            int col_local = wn * 64 + nt * 8 + (lane & 3) * 2 + q;
                            float s = e2s[col_local] + acc[mt][nt][h * 2 + q];
                            int col = ct * NT + col_local;
                            if (s < bv[slot]) { bv[slot] = s; bi[slot] = col; }
                        }
                }
        }
    }

    // ---- cross-thread argmin reduce (reuse B smem region) ----
    __syncthreads();
    float* redv = (float*)(smem + SM_B);
    int*   redi = (int*)(smem + SM_B + 8192);
#pragma unroll
    for (int slot = 0; slot < 8; slot++) {
        int row_local = wm * 64 + (slot >> 1) * 16 + (slot & 1) * 8 + (lane >> 2);
        int j = wn * 4 + (lane & 3);
        redv[row_local * 16 + j] = bv[slot];
        redi[row_local * 16 + j] = bi[slot];
    }
    __syncthreads();

    if (tid < 128) {
        float bvv = 3.4e38f;
        int bii = M_CODE;
#pragma unroll
        for (int j = 0; j < 16; j++) {
            float v = redv[tid * 16 + j];
            int i = redi[tid * 16 + j];
            if (v < bvv || (v == bvv && i < bii)) { bvv = v; bii = i; }
        }
        fidx[tid] = bii;
        idx_out[row0 + tid] = (float)bii;
        atomicAdd(&g_counts[bii], 1);
    }
    __syncthreads();

    // ---- gather quantized rows + loss partial ----
    float lsum = 0.0f;
    for (int e = tid; e < 128 * D_DIM; e += 256) {
        int r = e >> 8, k = e & 255;
        float q = embed[(size_t)fidx[r] * D_DIM + k];
        float xv = x[(size_t)(row0 + r) * D_DIM + k];
        quant_out[(size_t)(row0 + r) * D_DIM + k] = q;
        float dd = q - xv;
        lsum += dd * dd;
    }
    float* lred = (float*)(smem + SM_B + 16384);
    lred[tid] = lsum;
    __syncthreads();
#pragma unroll
    for (int s = 128; s > 0; s >>= 1) {
        if (tid < s) lred[tid] += lred[tid + s];
        __syncthreads();
    }
    if (tid == 0) atomicAdd(&g_loss_sum, lred[0]);
}

// ------------------------------ finalize -------------------------------------
__global__ void vq_finalize_kernel(float* __restrict__ loss_out,
                                   float* __restrict__ perp_out) {
    __shared__ float hred[256];
    int tid = threadIdx.x;
    float h = 0.0f;
    for (int m = tid; m < M_CODE; m += 256) {
        float p = (float)g_counts[m] * (1.0f / (float)N_TOK);
        h += p * logf(p + 1e-10f);
    }
    hred[tid] = h;
    __syncthreads();
#pragma unroll
    for (int s = 128; s > 0; s >>= 1) {
        if (tid < s) hred[tid] += hred[tid + s];
        __syncthreads();
    }
    if (tid == 0) {
        *loss_out = 1.25f * g_loss_sum / (float)((size_t)N_TOK * D_DIM);
        *perp_out = expf(-hred[0]);
    }
}

// ------------------------------ launch ---------------------------------------
extern "C" void kernel_launch(void* const* d_in, const int* in_sizes, int n_in,
                              void* d_out, int out_size) {
    const float* x = (const float*)d_in[0];      // [N, D]
    const float* embed = (const float*)d_in[1];  // [M, D]

    float* out = (float*)d_out;
    float* quant = out;
    float* idxp  = out + (size_t)N_TOK * D_DIM;
    float* lossp = idxp + N_TOK;
    float* perpp = lossp + 1;

    cudaFuncSetAttribute(vq_main_kernel,
                         cudaFuncAttributeMaxDynamicSharedMemorySize, SMEM_TOTAL);

    vq_init_kernel<<<(M_CODE + 255) / 256, 256>>>();
    vq_e2_kernel<<<(M_CODE + 255) / 256, 256>>>(embed);
    vq_split_kernel<<<(M_CODE * D_DIM / 4 + 255) / 256, 256>>>(embed);
    vq_main_kernel<<<N_TOK / 128, 256, SMEM_TOTAL>>>(x, embed, quant, idxp);
    vq_finalize_kernel<<<1, 256>>>(lossp, perpp);
}

// round 5
// speedup vs baseline: 2.7969x; 1.0099x over previous
#include <cuda_runtime.h>
#include <cuda_fp16.h>
#include <math.h>
#include <stdint.h>

#define N_TOK 32768
#define M_CODE 4096
#define D_DIM 256
#define NT 256                        // codes per tile
#define CT_COUNT (M_CODE / NT)        // 16
#define CHUNKS (CT_COUNT * 8)         // 128 chunks of 32 k

// ---------------- smem layout (bytes) ----------------
#define A_PITCH 264                    // halves per row (256 + 8 pad)
#define A_SPLIT 67584                  // 128 * 264 * 2
#define SM_A    0                      // [2 splits][128 rows][264 halves]
#define SM_B    135168
#define B_BUF   40960                  // per double-buffer
#define B_SPLIT 20480                  // per split within buffer
#define B_PITCH 40                     // halves per row (32 + 8 pad)
#define SM_E2   217088                 // 256 floats
#define SM_FIDX 218112                 // 128 ints
#define SMEM_TOTAL 218624

__device__ float g_e2[M_CODE];
__device__ int   g_counts[M_CODE];
__device__ float g_loss_sum;
__device__ __align__(16) __half g_eh[M_CODE * D_DIM];
__device__ __align__(16) __half g_el[M_CODE * D_DIM];

// ---------------------------- helpers ----------------------------------
__device__ __forceinline__ uint32_t smem_u32(const void* p) {
    uint32_t a;
    asm("{ .reg .u64 t; cvta.to.shared.u64 t, %1; cvt.u32.u64 %0, t; }"
        : "=r"(a) : "l"(p));
    return a;
}
__device__ __forceinline__ uint32_t lds32(uint32_t a) {
    uint32_t v;
    asm volatile("ld.shared.b32 %0, [%1];" : "=r"(v) : "r"(a));
    return v;
}
__device__ __forceinline__ void cp16(uint32_t dst, const void* src) {
    asm volatile("cp.async.cg.shared.global [%0], [%1], 16;"
                 :: "r"(dst), "l"(src) : "memory");
}
__device__ __forceinline__ void cp_commit() {
    asm volatile("cp.async.commit_group;" ::: "memory");
}
__device__ __forceinline__ void cp_wait1() {
    asm volatile("cp.async.wait_group 1;" ::: "memory");
}
__device__ __forceinline__ void mma16816(float* c, const uint32_t* a, const uint32_t* b) {
    asm volatile(
        "mma.sync.aligned.m16n8k16.row.col.f32.f16.f16.f32 "
        "{%0,%1,%2,%3}, {%4,%5,%6,%7}, {%8,%9}, {%0,%1,%2,%3};"
        : "+f"(c[0]), "+f"(c[1]), "+f"(c[2]), "+f"(c[3])
        : "r"(a[0]), "r"(a[1]), "r"(a[2]), "r"(a[3]), "r"(b[0]), "r"(b[1]));
}

// ----------------------------- small kernels --------------------------------
__global__ void vq_init_kernel() {
    int t = blockIdx.x * blockDim.x + threadIdx.x;
    if (t < M_CODE) g_counts[t] = 0;
    if (t == 0) g_loss_sum = 0.0f;
}
__global__ void vq_e2_kernel(const float* __restrict__ embed) {
    int m = blockIdx.x * blockDim.x + threadIdx.x;
    if (m >= M_CODE) return;
    const float4* row = reinterpret_cast<const float4*>(embed + (size_t)m * D_DIM);
    float s = 0.0f;
#pragma unroll
    for (int i = 0; i < D_DIM / 4; i++) {
        float4 v = row[i];
        s += v.x * v.x + v.y * v.y + v.z * v.z + v.w * v.w;
    }
    g_e2[m] = s;
}
// split embed into fp16 hi/lo
__global__ void vq_split_kernel(const float* __restrict__ embed) {
    int i = blockIdx.x * blockDim.x + threadIdx.x;   // one float4 each
    if (i >= M_CODE * D_DIM / 4) return;
    float4 v = reinterpret_cast<const float4*>(embed)[i];
    __half hx = __float2half_rn(v.x), hy = __float2half_rn(v.y);
    __half hz = __float2half_rn(v.z), hw = __float2half_rn(v.w);
    __half lx = __float2half_rn(v.x - __half2float(hx));
    __half ly = __float2half_rn(v.y - __half2float(hy));
    __half lz = __float2half_rn(v.z - __half2float(hz));
    __half lw = __float2half_rn(v.w - __half2float(hw));
    half2* ph = reinterpret_cast<half2*>(g_eh);
    half2* pl = reinterpret_cast<half2*>(g_el);
    ph[i * 2 + 0] = __halves2half2(hx, hy);
    ph[i * 2 + 1] = __halves2half2(hz, hw);
    pl[i * 2 + 0] = __halves2half2(lx, ly);
    pl[i * 2 + 1] = __halves2half2(lz, lw);
}

// ------------------------------ main kernel ---------------------------------
__global__ __launch_bounds__(256, 1)
void vq_main_kernel(const float* __restrict__ x,
                    const float* __restrict__ embed,
                    float* __restrict__ quant_out,
                    float* __restrict__ idx_out) {
    extern __shared__ char smem[];
    const uint32_t sb = smem_u32(smem);
    const int tid = threadIdx.x;
    const int lane = tid & 31;
    const int wid = tid >> 5;
    const int wm = wid >> 2;        // 0..1 (m block of 64 rows)
    const int wn = wid & 3;         // 0..3 (n block of 64 cols)
    const int row0 = blockIdx.x * 128;

    float* e2s = (float*)(smem + SM_E2);
    int* fidx = (int*)(smem + SM_FIDX);

    // ---- stage x: split to fp16 hi/lo into smem [-2*x] ----
    for (int i = tid; i < 128 * 64; i += 256) {     // 8192 float4
        int row = i >> 6;
        int kq = (i & 63) << 2;
        float4 v = *(const float4*)(x + (size_t)(row0 + row) * D_DIM + kq);
        float ax = -2.0f * v.x, ay = -2.0f * v.y, az = -2.0f * v.z, aw = -2.0f * v.w;
        __half hx = __float2half_rn(ax), hy = __float2half_rn(ay);
        __half hz = __float2half_rn(az), hw = __float2half_rn(aw);
        __half lx = __float2half_rn(ax - __half2float(hx));
        __half ly = __float2half_rn(ay - __half2float(hy));
        __half lz = __float2half_rn(az - __half2float(hz));
        __half lw = __float2half_rn(aw - __half2float(hw));
        half2* dh = (half2*)(smem + SM_A + (size_t)(row * A_PITCH + kq) * 2);
        half2* dl = (half2*)(smem + SM_A + A_SPLIT + (size_t)(row * A_PITCH + kq) * 2);
        dh[0] = __halves2half2(hx, hy);
        dh[1] = __halves2half2(hz, hw);
        dl[0] = __halves2half2(lx, ly);
        dl[1] = __halves2half2(lz, lw);
    }

    // ---- prologue: async-load B chunk 0 ----
    {
        const __half* srcs[2] = {g_eh, g_el};
#pragma unroll
        for (int s = 0; s < 2; s++) {
            const __half* src = srcs[s] + (size_t)tid * D_DIM;   // ct=0,kc=0
            uint32_t dst = sb + SM_B + s * B_SPLIT + tid * (B_PITCH * 2);
#pragma unroll
            for (int j = 0; j < 4; j++) cp16(dst + j * 16, src + j * 8);
        }
        cp_commit();
    }

    float acc[4][8][4];
    float bv[8];
    int bi[8];
#pragma unroll
    for (int s = 0; s < 8; s++) { bv[s] = 3.4e38f; bi[s] = 0; }

    for (int c = 0; c < CHUNKS; c++) {
        const int ct = c >> 3, kc = c & 7, buf = c & 1;

        // Barrier: previous compute's reads of buffer (c+1)&1 must finish
        // before this iteration's prefetch overwrites it.
        if (c) __syncthreads();

        // prefetch chunk c+1
        if (c + 1 < CHUNKS) {
            const int nct = (c + 1) >> 3, nkc = (c + 1) & 7, nbuf = (c + 1) & 1;
            const __half* srcs[2] = {g_eh, g_el};
#pragma unroll
            for (int s = 0; s < 2; s++) {
                const __half* src = srcs[s] + (size_t)(nct * NT + tid) * D_DIM + nkc * 32;
                uint32_t dst = sb + SM_B + nbuf * B_BUF + s * B_SPLIT + tid * (B_PITCH * 2);
#pragma unroll
                for (int j = 0; j < 4; j++) cp16(dst + j * 16, src + j * 8);
            }
        }
        cp_commit();
        cp_wait1();
        __syncthreads();

        if (kc == 0) {
#pragma unroll
            for (int mt = 0; mt < 4; mt++)
#pragma unroll
                for (int nt = 0; nt < 8; nt++)
#pragma unroll
                    for (int q = 0; q < 4; q++) acc[mt][nt][q] = 0.0f;
            e2s[tid] = g_e2[ct * NT + tid];
        }

        // ---- compute: 2 k-steps of 16 ----
#pragma unroll
        for (int ks = 0; ks < 2; ks++) {
            const int kk = kc * 32 + ks * 16 + (lane & 3) * 2;   // global k for A
            const int kl = ks * 16 + (lane & 3) * 2;             // chunk-local k for B

            uint32_t a[2][4][4];
#pragma unroll
            for (int s = 0; s < 2; s++)
#pragma unroll
                for (int mt = 0; mt < 4; mt++) {
                    int ar = wm * 64 + mt * 16 + (lane >> 2);
                    uint32_t base = sb + SM_A + s * A_SPLIT + (ar * A_PITCH + kk) * 2;
                    a[s][mt][0] = lds32(base);
                    a[s][mt][1] = lds32(base + 8 * A_PITCH * 2);
                    a[s][mt][2] = lds32(base + 16);
                    a[s][mt][3] = lds32(base + 8 * A_PITCH * 2 + 16);
                }

            uint32_t bh[8][2], bl[8][2];
#pragma unroll
            for (int nt = 0; nt < 8; nt++) {
                int n = wn * 64 + nt * 8 + (lane >> 2);
                uint32_t base = sb + SM_B + buf * B_BUF + (n * B_PITCH + kl) * 2;
                bh[nt][0] = lds32(base);
                bh[nt][1] = lds32(base + 16);
                bl[nt][0] = lds32(base + B_SPLIT);
                bl[nt][1] = lds32(base + B_SPLIT + 16);
            }

            // --- sweep 1: hh (32 independent MMAs) ---
#pragma unroll
            for (int mt = 0; mt < 4; mt++)
#pragma unroll
                for (int nt = 0; nt < 8; nt++)
                    mma16816(acc[mt][nt], a[0][mt], bh[nt]);
            // --- sweep 2: lh (RAW distance 32 from sweep 1) ---
#pragma unroll
            for (int mt = 0; mt < 4; mt++)
#pragma unroll
                for (int nt = 0; nt < 8; nt++)
                    mma16816(acc[mt][nt], a[1][mt], bh[nt]);
            // --- sweep 3: hl ---
#pragma unroll
            for (int mt = 0; mt < 4; mt++)
#pragma unroll
                for (int nt = 0; nt < 8; nt++)
                    mma16816(acc[mt][nt], a[0][mt], bl[nt]);
        }

        // ---- epilogue of this code tile: fold e2, running argmin ----
        if (kc == 7) {
#pragma unroll
            for (int mt = 0; mt < 4; mt++)
#pragma unroll
                for (int h = 0; h < 2; h++) {
                    int slot = mt * 2 + h;
#pragma unroll
                    for (int nt = 0; nt < 8; nt++)
#pragma unroll
                        for (int q = 0; q < 2; q++) {
                            int col_local = wn * 64 + nt * 8 + (lane & 3) * 2 + q;
                            float s = e2s[col_local] + acc[mt][nt][h * 2 + q];
                            int col = ct * NT + col_local;
                            if (s < bv[slot]) { bv[slot] = s; bi[slot] = col; }
                        }
                }
        }
    }

    // ---- cross-thread argmin reduce (reuse B smem region) ----
    __syncthreads();
    float* redv = (float*)(smem + SM_B);
    int*   redi = (int*)(smem + SM_B + 8192);
#pragma unroll
    for (int slot = 0; slot < 8; slot++) {
        int row_local = wm * 64 + (slot >> 1) * 16 + (slot & 1) * 8 + (lane >> 2);
        int j = wn * 4 + (lane & 3);
        redv[row_local * 16 + j] = bv[slot];
        redi[row_local * 16 + j] = bi[slot];
    }
    __syncthreads();

    if (tid < 128) {
        float bvv = 3.4e38f;
        int bii = M_CODE;
#pragma unroll
        for (int j = 0; j < 16; j++) {
            float v = redv[tid * 16 + j];
            int i = redi[tid * 16 + j];
            if (v < bvv || (v == bvv && i < bii)) { bvv = v; bii = i; }
        }
        fidx[tid] = bii;
        idx_out[row0 + tid] = (float)bii;
        atomicAdd(&g_counts[bii], 1);
    }
    __syncthreads();

    // ---- gather quantized rows + loss partial ----
    float lsum = 0.0f;
    for (int e = tid; e < 128 * D_DIM; e += 256) {
        int r = e >> 8, k = e & 255;
        float q = embed[(size_t)fidx[r] * D_DIM + k];
        float xv = x[(size_t)(row0 + r) * D_DIM + k];
        quant_out[(size_t)(row0 + r) * D_DIM + k] = q;
        float dd = q - xv;
        lsum += dd * dd;
    }
    float* lred = (float*)(smem + SM_B + 16384);
    lred[tid] = lsum;
    __syncthreads();
#pragma unroll
    for (int s = 128; s > 0; s >>= 1) {
        if (tid < s) lred[tid] += lred[tid + s];
        __syncthreads();
    }
    if (tid == 0) atomicAdd(&g_loss_sum, lred[0]);
}

// ------------------------------ finalize -------------------------------------
__global__ void vq_finalize_kernel(float* __restrict__ loss_out,
                                   float* __restrict__ perp_out) {
    __shared__ float hred[256];
    int tid = threadIdx.x;
    float h = 0.0f;
    for (int m = tid; m < M_CODE; m += 256) {
        float p = (float)g_counts[m] * (1.0f / (float)N_TOK);
        h += p * logf(p + 1e-10f);
    }
    hred[tid] = h;
    __syncthreads();
#pragma unroll
    for (int s = 128; s > 0; s >>= 1) {
        if (tid < s) hred[tid] += hred[tid + s];
        __syncthreads();
    }
    if (tid == 0) {
        *loss_out = 1.25f * g_loss_sum / (float)((size_t)N_TOK * D_DIM);
        *perp_out = expf(-hred[0]);
    }
}

// ------------------------------ launch ---------------------------------------
extern "C" void kernel_launch(void* const* d_in, const int* in_sizes, int n_in,
                              void* d_out, int out_size) {
    const float* x = (const float*)d_in[0];      // [N, D]
    const float* embed = (const float*)d_in[1];  // [M, D]

    float* out = (float*)d_out;
    float* quant = out;
    float* idxp  = out + (size_t)N_TOK * D_DIM;
    float* lossp = idxp + N_TOK;
    float* perpp = lossp + 1;

    cudaFuncSetAttribute(vq_main_kernel,
                         cudaFuncAttributeMaxDynamicSharedMemorySize, SMEM_TOTAL);

    vq_init_kernel<<<(M_CODE + 255) / 256, 256>>>();
    vq_e2_kernel<<<(M_CODE + 255) / 256, 256>>>(embed);
    vq_split_kernel<<<(M_CODE * D_DIM / 4 + 255) / 256, 256>>>(embed);
    vq_main_kernel<<<N_TOK / 128, 256, SMEM_TOTAL>>>(x, embed, quant, idxp);
    vq_finalize_kernel<<<1, 256>>>(lossp, perpp);
}

// round 6
// speedup vs baseline: 3.6344x; 1.2994x over previous
#include <cuda_runtime.h>
#include <cuda_fp16.h>
#include <math.h>
#include <stdint.h>

#define N_TOK 32768
#define M_CODE 4096
#define D_DIM 256
#define NT 256                        // codes per tile
#define CT_COUNT (M_CODE / NT)        // 16
#define CHUNKS (CT_COUNT * 8)         // 128 chunks of 32 k

// ---------------- smem layout (bytes) ----------------
#define A_PITCH 264                    // halves per row (256 + 8 pad)
#define A_SPLIT 67584                  // 128 * 264 * 2
#define SM_A    0                      // [2 splits][128 rows][264 halves]
#define SM_B    135168                 // per-warp private slices
#define BW_WARP 10240                  // bytes per warp (2 buf x 2 split x 2560)
#define BW_BUF  5120                   // per buffer within warp
#define BW_SPLIT 2560                  // per split within buffer (32 rows x 80B)
#define B_PITCH 40                     // halves per row (32 + 8 pad)
#define SM_E2   217088                 // (unused spare)
#define SM_FIDX 218112                 // 128 ints
#define SMEM_TOTAL 218624

__device__ float g_e2[M_CODE];
__device__ int   g_counts[M_CODE];
__device__ float g_loss_sum;
__device__ __align__(16) __half g_eh[M_CODE * D_DIM];
__device__ __align__(16) __half g_el[M_CODE * D_DIM];

// ---------------------------- helpers ----------------------------------
__device__ __forceinline__ uint32_t smem_u32(const void* p) {
    uint32_t a;
    asm("{ .reg .u64 t; cvta.to.shared.u64 t, %1; cvt.u32.u64 %0, t; }"
        : "=r"(a) : "l"(p));
    return a;
}
__device__ __forceinline__ uint32_t lds32(uint32_t a) {
    uint32_t v;
    asm volatile("ld.shared.b32 %0, [%1];" : "=r"(v) : "r"(a));
    return v;
}
__device__ __forceinline__ void cp16(uint32_t dst, const void* src) {
    asm volatile("cp.async.cg.shared.global [%0], [%1], 16;"
                 :: "r"(dst), "l"(src) : "memory");
}
__device__ __forceinline__ void cp_commit() {
    asm volatile("cp.async.commit_group;" ::: "memory");
}
__device__ __forceinline__ void cp_wait1() {
    asm volatile("cp.async.wait_group 1;" ::: "memory");
}
__device__ __forceinline__ void mma16816(float* c, const uint32_t* a, const uint32_t* b) {
    asm volatile(
        "mma.sync.aligned.m16n8k16.row.col.f32.f16.f16.f32 "
        "{%0,%1,%2,%3}, {%4,%5,%6,%7}, {%8,%9}, {%0,%1,%2,%3};"
        : "+f"(c[0]), "+f"(c[1]), "+f"(c[2]), "+f"(c[3])
        : "r"(a[0]), "r"(a[1]), "r"(a[2]), "r"(a[3]), "r"(b[0]), "r"(b[1]));
}

// ----------------------------- small kernels --------------------------------
__global__ void vq_init_kernel() {
    int t = blockIdx.x * blockDim.x + threadIdx.x;
    if (t < M_CODE) g_counts[t] = 0;
    if (t == 0) g_loss_sum = 0.0f;
}
__global__ void vq_e2_kernel(const float* __restrict__ embed) {
    int m = blockIdx.x * blockDim.x + threadIdx.x;
    if (m >= M_CODE) return;
    const float4* row = reinterpret_cast<const float4*>(embed + (size_t)m * D_DIM);
    float s = 0.0f;
#pragma unroll
    for (int i = 0; i < D_DIM / 4; i++) {
        float4 v = row[i];
        s += v.x * v.x + v.y * v.y + v.z * v.z + v.w * v.w;
    }
    g_e2[m] = s;
}
__global__ void vq_split_kernel(const float* __restrict__ embed) {
    int i = blockIdx.x * blockDim.x + threadIdx.x;   // one float4 each
    if (i >= M_CODE * D_DIM / 4) return;
    float4 v = reinterpret_cast<const float4*>(embed)[i];
    __half hx = __float2half_rn(v.x), hy = __float2half_rn(v.y);
    __half hz = __float2half_rn(v.z), hw = __float2half_rn(v.w);
    __half lx = __float2half_rn(v.x - __half2float(hx));
    __half ly = __float2half_rn(v.y - __half2float(hy));
    __half lz = __float2half_rn(v.z - __half2float(hz));
    __half lw = __float2half_rn(v.w - __half2float(hw));
    half2* ph = reinterpret_cast<half2*>(g_eh);
    half2* pl = reinterpret_cast<half2*>(g_el);
    ph[i * 2 + 0] = __halves2half2(hx, hy);
    ph[i * 2 + 1] = __halves2half2(hz, hw);
    pl[i * 2 + 0] = __halves2half2(lx, ly);
    pl[i * 2 + 1] = __halves2half2(lz, lw);
}

// ------------------------------ main kernel ---------------------------------
__global__ __launch_bounds__(256, 1)
void vq_main_kernel(const float* __restrict__ x,
                    const float* __restrict__ embed,
                    float* __restrict__ quant_out,
                    float* __restrict__ idx_out) {
    extern __shared__ char smem[];
    const uint32_t sb = smem_u32(smem);
    const int tid = threadIdx.x;
    const int lane = tid & 31;
    const int wid = tid >> 5;            // warp owns column stripe wid*32..+32
    const int row0 = blockIdx.x * 128;

    int* fidx = (int*)(smem + SM_FIDX);
    const uint32_t wB = sb + SM_B + wid * BW_WARP;

    // ---- per-warp prologue: async-load own B slice for chunk 0 ----
    {
        const int code = 0 * NT + wid * 32 + lane;   // ct=0
        const __half* srch = g_eh + (size_t)code * D_DIM;  // kc=0
        const __half* srcl = g_el + (size_t)code * D_DIM;
        uint32_t dst = wB + lane * (B_PITCH * 2);
#pragma unroll
        for (int j = 0; j < 4; j++) cp16(dst + j * 16, srch + j * 8);
#pragma unroll
        for (int j = 0; j < 4; j++) cp16(dst + BW_SPLIT + j * 16, srcl + j * 8);
        cp_commit();
    }

    // ---- stage x: split to fp16 hi/lo into smem [-2*x] ----
    for (int i = tid; i < 128 * 64; i += 256) {     // 8192 float4
        int row = i >> 6;
        int kq = (i & 63) << 2;
        float4 v = *(const float4*)(x + (size_t)(row0 + row) * D_DIM + kq);
        float ax = -2.0f * v.x, ay = -2.0f * v.y, az = -2.0f * v.z, aw = -2.0f * v.w;
        __half hx = __float2half_rn(ax), hy = __float2half_rn(ay);
        __half hz = __float2half_rn(az), hw = __float2half_rn(aw);
        __half lx = __float2half_rn(ax - __half2float(hx));
        __half ly = __float2half_rn(ay - __half2float(hy));
        __half lz = __float2half_rn(az - __half2float(hz));
        __half lw = __float2half_rn(aw - __half2float(hw));
        half2* dh = (half2*)(smem + SM_A + (size_t)(row * A_PITCH + kq) * 2);
        half2* dl = (half2*)(smem + SM_A + A_SPLIT + (size_t)(row * A_PITCH + kq) * 2);
        dh[0] = __halves2half2(hx, hy);
        dh[1] = __halves2half2(hz, hw);
        dl[0] = __halves2half2(lx, ly);
        dl[1] = __halves2half2(lz, lw);
    }
    __syncthreads();    // the ONLY pre-loop barrier: A tile visible to all warps

    float acc[8][4][4];
    float e2r[8];
    float bv[16];
    int bi[16];
#pragma unroll
    for (int s = 0; s < 16; s++) { bv[s] = 3.4e38f; bi[s] = 0; }

    // ======== barrier-free mainloop: warps fully decoupled ========
    for (int c = 0; c < CHUNKS; c++) {
        const int ct = c >> 3, kc = c & 7, buf = c & 1;

        // per-warp prefetch of chunk c+1 into own slice (other buffer)
        if (c + 1 < CHUNKS) {
            const int nct = (c + 1) >> 3, nkc = (c + 1) & 7, nbuf = (c + 1) & 1;
            const int code = nct * NT + wid * 32 + lane;
            const __half* srch = g_eh + (size_t)code * D_DIM + nkc * 32;
            const __half* srcl = g_el + (size_t)code * D_DIM + nkc * 32;
            uint32_t dst = wB + nbuf * BW_BUF + lane * (B_PITCH * 2);
#pragma unroll
            for (int j = 0; j < 4; j++) cp16(dst + j * 16, srch + j * 8);
#pragma unroll
            for (int j = 0; j < 4; j++) cp16(dst + BW_SPLIT + j * 16, srcl + j * 8);
        }
        cp_commit();
        cp_wait1();        // chunk c's slice now resident (per-thread ordering)

        if (kc == 0) {
#pragma unroll
            for (int mt = 0; mt < 8; mt++)
#pragma unroll
                for (int nt = 0; nt < 4; nt++)
#pragma unroll
                    for (int q = 0; q < 4; q++) acc[mt][nt][q] = 0.0f;
#pragma unroll
            for (int nt = 0; nt < 4; nt++)
#pragma unroll
                for (int q = 0; q < 2; q++)
                    e2r[nt * 2 + q] =
                        __ldg(&g_e2[ct * NT + wid * 32 + nt * 8 + (lane & 3) * 2 + q]);
        }

        // ---- compute: 2 k-steps of 16 ----
#pragma unroll
        for (int ks = 0; ks < 2; ks++) {
            const int kk = kc * 32 + ks * 16 + (lane & 3) * 2;   // global k for A
            const int kl = ks * 16 + (lane & 3) * 2;             // chunk-local k for B

            uint32_t b[4][2][2];   // [nt][split][reg]
#pragma unroll
            for (int nt = 0; nt < 4; nt++) {
                int n = nt * 8 + (lane >> 2);
                uint32_t base = wB + buf * BW_BUF + (n * B_PITCH + kl) * 2;
                b[nt][0][0] = lds32(base);
                b[nt][0][1] = lds32(base + 16);
                b[nt][1][0] = lds32(base + BW_SPLIT);
                b[nt][1][1] = lds32(base + BW_SPLIT + 16);
            }

            uint32_t a[8][4];
            // --- a = A_hi; sweeps hh then hl (a reused) ---
#pragma unroll
            for (int mt = 0; mt < 8; mt++) {
                int ar = mt * 16 + (lane >> 2);
                uint32_t base = sb + SM_A + (ar * A_PITCH + kk) * 2;
                a[mt][0] = lds32(base);
                a[mt][1] = lds32(base + 8 * A_PITCH * 2);
                a[mt][2] = lds32(base + 16);
                a[mt][3] = lds32(base + 8 * A_PITCH * 2 + 16);
            }
#pragma unroll
            for (int mt = 0; mt < 8; mt++)
#pragma unroll
                for (int nt = 0; nt < 4; nt++)
                    mma16816(acc[mt][nt], a[mt], b[nt][0]);
#pragma unroll
            for (int mt = 0; mt < 8; mt++)
#pragma unroll
                for (int nt = 0; nt < 4; nt++)
                    mma16816(acc[mt][nt], a[mt], b[nt][1]);
            // --- a = A_lo; sweep lh ---
#pragma unroll
            for (int mt = 0; mt < 8; mt++) {
                int ar = mt * 16 + (lane >> 2);
                uint32_t base = sb + SM_A + A_SPLIT + (ar * A_PITCH + kk) * 2;
                a[mt][0] = lds32(base);
                a[mt][1] = lds32(base + 8 * A_PITCH * 2);
                a[mt][2] = lds32(base + 16);
                a[mt][3] = lds32(base + 8 * A_PITCH * 2 + 16);
            }
#pragma unroll
            for (int mt = 0; mt < 8; mt++)
#pragma unroll
                for (int nt = 0; nt < 4; nt++)
                    mma16816(acc[mt][nt], a[mt], b[nt][0]);
        }

        // ---- epilogue of this code tile: fold e2, running argmin ----
        if (kc == 7) {
#pragma unroll
            for (int mt = 0; mt < 8; mt++)
#pragma unroll
                for (int h = 0; h < 2; h++) {
                    int slot = mt * 2 + h;
#pragma unroll
                    for (int nt = 0; nt < 4; nt++)
#pragma unroll
                        for (int q = 0; q < 2; q++) {
                            float s = e2r[nt * 2 + q] + acc[mt][nt][h * 2 + q];
                            int col = ct * NT + wid * 32 + nt * 8 + (lane & 3) * 2 + q;
                            if (s < bv[slot]) { bv[slot] = s; bi[slot] = col; }
                        }
                }
        }
    }

    // ---- cross-thread argmin reduce (reuse B smem region) ----
    __syncthreads();
    float* redv = (float*)(smem + SM_B);
    int*   redi = (int*)(smem + SM_B + 16384);
#pragma unroll
    for (int slot = 0; slot < 16; slot++) {
        int row_local = (slot >> 1) * 16 + (slot & 1) * 8 + (lane >> 2);
        int j = wid * 4 + (lane & 3);
        redv[row_local * 32 + j] = bv[slot];
        redi[row_local * 32 + j] = bi[slot];
    }
    __syncthreads();

    if (tid < 128) {
        float bvv = 3.4e38f;
        int bii = M_CODE;
#pragma unroll
        for (int j = 0; j < 32; j++) {
            float v = redv[tid * 32 + j];
            int i = redi[tid * 32 + j];
            if (v < bvv || (v == bvv && i < bii)) { bvv = v; bii = i; }
        }
        fidx[tid] = bii;
        idx_out[row0 + tid] = (float)bii;
        atomicAdd(&g_counts[bii], 1);
    }
    __syncthreads();

    // ---- gather quantized rows + loss partial ----
    float lsum = 0.0f;
    for (int e = tid; e < 128 * D_DIM; e += 256) {
        int r = e >> 8, k = e & 255;
        float q = embed[(size_t)fidx[r] * D_DIM + k];
        float xv = x[(size_t)(row0 + r) * D_DIM + k];
        quant_out[(size_t)(row0 + r) * D_DIM + k] = q;
        float dd = q - xv;
        lsum += dd * dd;
    }
    float* lred = (float*)(smem + SM_B + 32768);
    lred[tid] = lsum;
    __syncthreads();
#pragma unroll
    for (int s = 128; s > 0; s >>= 1) {
        if (tid < s) lred[tid] += lred[tid + s];
        __syncthreads();
    }
    if (tid == 0) atomicAdd(&g_loss_sum, lred[0]);
}

// ------------------------------ finalize -------------------------------------
__global__ void vq_finalize_kernel(float* __restrict__ loss_out,
                                   float* __restrict__ perp_out) {
    __shared__ float hred[256];
    int tid = threadIdx.x;
    float h = 0.0f;
    for (int m = tid; m < M_CODE; m += 256) {
        float p = (float)g_counts[m] * (1.0f / (float)N_TOK);
        h += p * logf(p + 1e-10f);
    }
    hred[tid] = h;
    __syncthreads();
#pragma unroll
    for (int s = 128; s > 0; s >>= 1) {
        if (tid < s) hred[tid] += hred[tid + s];
        __syncthreads();
    }
    if (tid == 0) {
        *loss_out = 1.25f * g_loss_sum / (float)((size_t)N_TOK * D_DIM);
        *perp_out = expf(-hred[0]);
    }
}

// ------------------------------ launch ---------------------------------------
extern "C" void kernel_launch(void* const* d_in, const int* in_sizes, int n_in,
                              void* d_out, int out_size) {
    const float* x = (const float*)d_in[0];      // [N, D]
    const float* embed = (const float*)d_in[1];  // [M, D]

    float* out = (float*)d_out;
    float* quant = out;
    float* idxp  = out + (size_t)N_TOK * D_DIM;
    float* lossp = idxp + N_TOK;
    float* perpp = lossp + 1;

    cudaFuncSetAttribute(vq_main_kernel,
                         cudaFuncAttributeMaxDynamicSharedMemorySize, SMEM_TOTAL);

    vq_init_kernel<<<(M_CODE + 255) / 256, 256>>>();
    vq_e2_kernel<<<(M_CODE + 255) / 256, 256>>>(embed);
    vq_split_kernel<<<(M_CODE * D_DIM / 4 + 255) / 256, 256>>>(embed);
    vq_main_kernel<<<N_TOK / 128, 256, SMEM_TOTAL>>>(x, embed, quant, idxp);
    vq_finalize_kernel<<<1, 256>>>(lossp, perpp);
}

// round 7
// speedup vs baseline: 4.1058x; 1.1297x over previous
#include <cuda_runtime.h>
#include <cuda_fp16.h>
#include <math.h>
#include <stdint.h>

#define N_TOK 32768
#define M_CODE 4096
#define D_DIM 256
#define NT 256                        // codes per tile
#define CT_COUNT (M_CODE / NT)        // 16
#define CHUNKS (CT_COUNT * 8)         // 128 chunks of 32 k

// ---------------- smem layout (bytes) ----------------
#define A_PITCH 264                    // halves per row (256 + 8 pad)
#define A_SPLIT 67584                  // 128 * 264 * 2
#define SM_A    0                      // [2 splits][128 rows][264 halves]
#define SM_B    135168                 // per-warp private slices
#define BW_WARP 10240                  // bytes per warp (2 buf x 2 split x 2560)
#define BW_BUF  5120                   // per buffer within warp
#define BW_SPLIT 2560                  // per split within buffer (32 rows x 80B)
#define B_PITCH 40                     // halves per row (32 + 8 pad)
#define SM_FIDX 218112                 // 128 ints
#define SMEM_TOTAL 218624

__device__ float g_e2[M_CODE];
__device__ int   g_counts[M_CODE];
__device__ float g_loss_sum;
__device__ __align__(16) __half g_eh[M_CODE * D_DIM];
__device__ __align__(16) __half g_el[M_CODE * D_DIM];

// ---------------------------- helpers ----------------------------------
__device__ __forceinline__ uint32_t smem_u32(const void* p) {
    uint32_t a;
    asm("{ .reg .u64 t; cvta.to.shared.u64 t, %1; cvt.u32.u64 %0, t; }"
        : "=r"(a) : "l"(p));
    return a;
}
__device__ __forceinline__ void ldsm_x4(uint32_t& r0, uint32_t& r1,
                                        uint32_t& r2, uint32_t& r3, uint32_t a) {
    asm volatile("ldmatrix.sync.aligned.m8n8.x4.shared.b16 {%0,%1,%2,%3}, [%4];"
                 : "=r"(r0), "=r"(r1), "=r"(r2), "=r"(r3) : "r"(a));
}
__device__ __forceinline__ void cp16(uint32_t dst, const void* src) {
    asm volatile("cp.async.cg.shared.global [%0], [%1], 16;"
                 :: "r"(dst), "l"(src) : "memory");
}
__device__ __forceinline__ void cp_commit() {
    asm volatile("cp.async.commit_group;" ::: "memory");
}
__device__ __forceinline__ void cp_wait1() {
    asm volatile("cp.async.wait_group 1;" ::: "memory");
}
__device__ __forceinline__ void mma16816(float* c, const uint32_t* a, const uint32_t* b) {
    asm volatile(
        "mma.sync.aligned.m16n8k16.row.col.f32.f16.f16.f32 "
        "{%0,%1,%2,%3}, {%4,%5,%6,%7}, {%8,%9}, {%0,%1,%2,%3};"
        : "+f"(c[0]), "+f"(c[1]), "+f"(c[2]), "+f"(c[3])
        : "r"(a[0]), "r"(a[1]), "r"(a[2]), "r"(a[3]), "r"(b[0]), "r"(b[1]));
}

// ----------------------------- small kernels --------------------------------
__global__ void vq_init_kernel() {
    int t = blockIdx.x * blockDim.x + threadIdx.x;
    if (t < M_CODE) g_counts[t] = 0;
    if (t == 0) g_loss_sum = 0.0f;
}
__global__ void vq_e2_kernel(const float* __restrict__ embed) {
    int m = blockIdx.x * blockDim.x + threadIdx.x;
    if (m >= M_CODE) return;
    const float4* row = reinterpret_cast<const float4*>(embed + (size_t)m * D_DIM);
    float s = 0.0f;
#pragma unroll
    for (int i = 0; i < D_DIM / 4; i++) {
        float4 v = row[i];
        s += v.x * v.x + v.y * v.y + v.z * v.z + v.w * v.w;
    }
    g_e2[m] = s;
}
__global__ void vq_split_kernel(const float* __restrict__ embed) {
    int i = blockIdx.x * blockDim.x + threadIdx.x;   // one float4 each
    if (i >= M_CODE * D_DIM / 4) return;
    float4 v = reinterpret_cast<const float4*>(embed)[i];
    __half hx = __float2half_rn(v.x), hy = __float2half_rn(v.y);
    __half hz = __float2half_rn(v.z), hw = __float2half_rn(v.w);
    __half lx = __float2half_rn(v.x - __half2float(hx));
    __half ly = __float2half_rn(v.y - __half2float(hy));
    __half lz = __float2half_rn(v.z - __half2float(hz));
    __half lw = __float2half_rn(v.w - __half2float(hw));
    half2* ph = reinterpret_cast<half2*>(g_eh);
    half2* pl = reinterpret_cast<half2*>(g_el);
    ph[i * 2 + 0] = __halves2half2(hx, hy);
    ph[i * 2 + 1] = __halves2half2(hz, hw);
    pl[i * 2 + 0] = __halves2half2(lx, ly);
    pl[i * 2 + 1] = __halves2half2(lz, lw);
}

// ------------------------------ main kernel ---------------------------------
__global__ __launch_bounds__(256, 1)
void vq_main_kernel(const float* __restrict__ x,
                    const float* __restrict__ embed,
                    float* __restrict__ quant_out,
                    float* __restrict__ idx_out) {
    extern __shared__ char smem[];
    const uint32_t sb = smem_u32(smem);
    const int tid = threadIdx.x;
    const int lane = tid & 31;
    const int wid = tid >> 5;            // warp owns column stripe wid*32..+32
    const int row0 = blockIdx.x * 128;

    int* fidx = (int*)(smem + SM_FIDX);
    const uint32_t wB = sb + SM_B + wid * BW_WARP;

    // ldmatrix per-lane address offsets (bytes)
    //  A .x4: m0=rows0-7/k0-7, m1=rows8-15/k0-7, m2=rows0-7/k8-15, m3=rows8-15/k8-15
    const uint32_t aOff = ((uint32_t)(lane & 15) * A_PITCH + ((lane >> 4) & 1) * 8) * 2;
    //  B .x4: m0=n0-7/k0-7, m1=n0-7/k8-15, m2=n8-15/k0-7, m3=n8-15/k8-15
    const uint32_t bOff = (((uint32_t)(lane >> 4) * 8 + (lane & 7)) * B_PITCH +
                           ((lane >> 3) & 1) * 8) * 2;

    // ---- per-warp prologue: async-load own B slice for chunk 0 ----
    {
        const int code = wid * 32 + lane;   // ct=0
        const __half* srch = g_eh + (size_t)code * D_DIM;  // kc=0
        const __half* srcl = g_el + (size_t)code * D_DIM;
        uint32_t dst = wB + lane * (B_PITCH * 2);
#pragma unroll
        for (int j = 0; j < 4; j++) cp16(dst + j * 16, srch + j * 8);
#pragma unroll
        for (int j = 0; j < 4; j++) cp16(dst + BW_SPLIT + j * 16, srcl + j * 8);
        cp_commit();
    }

    // ---- stage x: split to fp16 hi/lo into smem [-2*x] ----
    for (int i = tid; i < 128 * 64; i += 256) {     // 8192 float4
        int row = i >> 6;
        int kq = (i & 63) << 2;
        float4 v = *(const float4*)(x + (size_t)(row0 + row) * D_DIM + kq);
        float ax = -2.0f * v.x, ay = -2.0f * v.y, az = -2.0f * v.z, aw = -2.0f * v.w;
        __half hx = __float2half_rn(ax), hy = __float2half_rn(ay);
        __half hz = __float2half_rn(az), hw = __float2half_rn(aw);
        __half lx = __float2half_rn(ax - __half2float(hx));
        __half ly = __float2half_rn(ay - __half2float(hy));
        __half lz = __float2half_rn(az - __half2float(hz));
        __half lw = __float2half_rn(aw - __half2float(hw));
        half2* dh = (half2*)(smem + SM_A + (size_t)(row * A_PITCH + kq) * 2);
        half2* dl = (half2*)(smem + SM_A + A_SPLIT + (size_t)(row * A_PITCH + kq) * 2);
        dh[0] = __halves2half2(hx, hy);
        dh[1] = __halves2half2(hz, hw);
        dl[0] = __halves2half2(lx, ly);
        dl[1] = __halves2half2(lz, lw);
    }
    __syncthreads();    // the ONLY pre-loop barrier: A tile visible to all warps

    float acc[8][4][4];
    float e2r[8];
    float bv[16];
    int bi[16];
#pragma unroll
    for (int s = 0; s < 16; s++) { bv[s] = 3.4e38f; bi[s] = 0; }

    // ======== barrier-free mainloop: warps fully decoupled ========
    for (int c = 0; c < CHUNKS; c++) {
        const int ct = c >> 3, kc = c & 7, buf = c & 1;

        // per-warp prefetch of chunk c+1 into own slice (other buffer)
        if (c + 1 < CHUNKS) {
            const int nct = (c + 1) >> 3, nkc = (c + 1) & 7, nbuf = (c + 1) & 1;
            const int code = nct * NT + wid * 32 + lane;
            const __half* srch = g_eh + (size_t)code * D_DIM + nkc * 32;
            const __half* srcl = g_el + (size_t)code * D_DIM + nkc * 32;
            uint32_t dst = wB + nbuf * BW_BUF + lane * (B_PITCH * 2);
#pragma unroll
            for (int j = 0; j < 4; j++) cp16(dst + j * 16, srch + j * 8);
#pragma unroll
            for (int j = 0; j < 4; j++) cp16(dst + BW_SPLIT + j * 16, srcl + j * 8);
        }
        cp_commit();
        cp_wait1();        // chunk c's slice now resident (per-thread ordering)

        if (kc == 0) {
#pragma unroll
            for (int mt = 0; mt < 8; mt++)
#pragma unroll
                for (int nt = 0; nt < 4; nt++)
#pragma unroll
                    for (int q = 0; q < 4; q++) acc[mt][nt][q] = 0.0f;
#pragma unroll
            for (int nt = 0; nt < 4; nt++)
#pragma unroll
                for (int q = 0; q < 2; q++)
                    e2r[nt * 2 + q] =
                        __ldg(&g_e2[ct * NT + wid * 32 + nt * 8 + (lane & 3) * 2 + q]);
        }

        // ---- compute: 2 k-steps of 16 ----
#pragma unroll
        for (int ks = 0; ks < 2; ks++) {
            const uint32_t kk0 = (kc * 32 + ks * 16) * 2;   // A k byte offset
            const uint32_t kl0 = (ks * 16) * 2;             // B k byte offset

            // B fragments: [nt][split][reg], 2 ldmatrix.x4 per split
            uint32_t b[4][2][2];
#pragma unroll
            for (int s = 0; s < 2; s++) {
                uint32_t base = wB + buf * BW_BUF + s * BW_SPLIT + bOff + kl0;
                ldsm_x4(b[0][s][0], b[0][s][1], b[1][s][0], b[1][s][1], base);
                ldsm_x4(b[2][s][0], b[2][s][1], b[3][s][0], b[3][s][1],
                        base + 16 * B_PITCH * 2);
            }

            uint32_t a[8][4];
            // --- a = A_hi; sweeps hh then hl (a reused) ---
            {
                uint32_t base = sb + SM_A + aOff + kk0;
#pragma unroll
                for (int mt = 0; mt < 8; mt++)
                    ldsm_x4(a[mt][0], a[mt][1], a[mt][2], a[mt][3],
                            base + mt * (16 * A_PITCH * 2));
            }
#pragma unroll
            for (int mt = 0; mt < 8; mt++)
#pragma unroll
                for (int nt = 0; nt < 4; nt++)
                    mma16816(acc[mt][nt], a[mt], b[nt][0]);
#pragma unroll
            for (int mt = 0; mt < 8; mt++)
#pragma unroll
                for (int nt = 0; nt < 4; nt++)
                    mma16816(acc[mt][nt], a[mt], b[nt][1]);
            // --- a = A_lo; sweep lh ---
            {
                uint32_t base = sb + SM_A + A_SPLIT + aOff + kk0;
#pragma unroll
                for (int mt = 0; mt < 8; mt++)
                    ldsm_x4(a[mt][0], a[mt][1], a[mt][2], a[mt][3],
                            base + mt * (16 * A_PITCH * 2));
            }
#pragma unroll
            for (int mt = 0; mt < 8; mt++)
#pragma unroll
                for (int nt = 0; nt < 4; nt++)
                    mma16816(acc[mt][nt], a[mt], b[nt][0]);
        }

        // ---- epilogue of this code tile: fold e2, running argmin ----
        if (kc == 7) {
#pragma unroll
            for (int mt = 0; mt < 8; mt++)
#pragma unroll
                for (int h = 0; h < 2; h++) {
                    int slot = mt * 2 + h;
#pragma unroll
                    for (int nt = 0; nt < 4; nt++)
#pragma unroll
                        for (int q = 0; q < 2; q++) {
                            float s = e2r[nt * 2 + q] + acc[mt][nt][h * 2 + q];
                            int col = ct * NT + wid * 32 + nt * 8 + (lane & 3) * 2 + q;
                            if (s < bv[slot]) { bv[slot] = s; bi[slot] = col; }
                        }
                }
        }
    }

    // ---- cross-thread argmin reduce (reuse B smem region) ----
    __syncthreads();
    float* redv = (float*)(smem + SM_B);
    int*   redi = (int*)(smem + SM_B + 16384);
#pragma unroll
    for (int slot = 0; slot < 16; slot++) {
        int row_local = (slot >> 1) * 16 + (slot & 1) * 8 + (lane >> 2);
        int j = wid * 4 + (lane & 3);
        redv[row_local * 32 + j] = bv[slot];
        redi[row_local * 32 + j] = bi[slot];
    }
    __syncthreads();

    if (tid < 128) {
        float bvv = 3.4e38f;
        int bii = M_CODE;
#pragma unroll
        for (int j = 0; j < 32; j++) {
            float v = redv[tid * 32 + j];
            int i = redi[tid * 32 + j];
            if (v < bvv || (v == bvv && i < bii)) { bvv = v; bii = i; }
        }
        fidx[tid] = bii;
        idx_out[row0 + tid] = (float)bii;
        atomicAdd(&g_counts[bii], 1);
    }
    __syncthreads();

    // ---- gather quantized rows + loss partial ----
    float lsum = 0.0f;
    for (int e = tid; e < 128 * D_DIM; e += 256) {
        int r = e >> 8, k = e & 255;
        float q = embed[(size_t)fidx[r] * D_DIM + k];
        float xv = x[(size_t)(row0 + r) * D_DIM + k];
        quant_out[(size_t)(row0 + r) * D_DIM + k] = q;
        float dd = q - xv;
        lsum += dd * dd;
    }
    float* lred = (float*)(smem + SM_B + 32768);
    lred[tid] = lsum;
    __syncthreads();
#pragma unroll
    for (int s = 128; s > 0; s >>= 1) {
        if (tid < s) lred[tid] += lred[tid + s];
        __syncthreads();
    }
    if (tid == 0) atomicAdd(&g_loss_sum, lred[0]);
}

// ------------------------------ finalize -------------------------------------
__global__ void vq_finalize_kernel(float* __restrict__ loss_out,
                                   float* __restrict__ perp_out) {
    __shared__ float hred[256];
    int tid = threadIdx.x;
    float h = 0.0f;
    for (int m = tid; m < M_CODE; m += 256) {
        float p = (float)g_counts[m] * (1.0f / (float)N_TOK);
        h += p * logf(p + 1e-10f);
    }
    hred[tid] = h;
    __syncthreads();
#pragma unroll
    for (int s = 128; s > 0; s >>= 1) {
        if (tid < s) hred[tid] += hred[tid + s];
        __syncthreads();
    }
    if (tid == 0) {
        *loss_out = 1.25f * g_loss_sum / (float)((size_t)N_TOK * D_DIM);
        *perp_out = expf(-hred[0]);
    }
}

// ------------------------------ launch ---------------------------------------
extern "C" void kernel_launch(void* const* d_in, const int* in_sizes, int n_in,
                              void* d_out, int out_size) {
    const float* x = (const float*)d_in[0];      // [N, D]
    const float* embed = (const float*)d_in[1];  // [M, D]

    float* out = (float*)d_out;
    float* quant = out;
    float* idxp  = out + (size_t)N_TOK * D_DIM;
    float* lossp = idxp + N_TOK;
    float* perpp = lossp + 1;

    cudaFuncSetAttribute(vq_main_kernel,
                         cudaFuncAttributeMaxDynamicSharedMemorySize, SMEM_TOTAL);

    vq_init_kernel<<<(M_CODE + 255) / 256, 256>>>();
    vq_e2_kernel<<<(M_CODE + 255) / 256, 256>>>(embed);
    vq_split_kernel<<<(M_CODE * D_DIM / 4 + 255) / 256, 256>>>(embed);
    vq_main_kernel<<<N_TOK / 128, 256, SMEM_TOTAL>>>(x, embed, quant, idxp);
    vq_finalize_kernel<<<1, 256>>>(lossp, perpp);
}

// round 8
// speedup vs baseline: 4.2592x; 1.0374x over previous
#include <cuda_runtime.h>
#include <cuda_fp16.h>
#include <math.h>
#include <stdint.h>

#define N_TOK 32768
#define M_CODE 4096
#define D_DIM 256
#define NT 128                        // codes per tile
#define CT_COUNT (M_CODE / NT)        // 32
#define CHUNKS (CT_COUNT * 8)         // 256 chunks of 32 k

// ---------------- smem layout (bytes) ----------------
#define A_PITCH 264                    // halves per row (256 + 8 pad)
#define A_SPLIT 67584                  // 128 * 264 * 2
#define SM_A    0                      // [2 splits][128 rows][264 halves]
#define SM_B    135168                 // per-warp private slices
#define BW_WARP 5120                   // bytes per warp (2 buf x 2 split x 1280)
#define BW_BUF  2560                   // per buffer within warp
#define BW_SPLIT 1280                  // per split within buffer (16 rows x 80B)
#define B_PITCH 40                     // halves per row (32 + 8 pad)
#define SM_FIDX 176640                 // 128 ints
#define SMEM_TOTAL 177152

__device__ float g_e2[M_CODE];
__device__ int   g_counts[M_CODE];
__device__ float g_loss_sum;
__device__ __align__(16) __half g_eh[M_CODE * D_DIM];
__device__ __align__(16) __half g_el[M_CODE * D_DIM];

// ---------------------------- helpers ----------------------------------
__device__ __forceinline__ uint32_t smem_u32(const void* p) {
    uint32_t a;
    asm("{ .reg .u64 t; cvta.to.shared.u64 t, %1; cvt.u32.u64 %0, t; }"
        : "=r"(a) : "l"(p));
    return a;
}
__device__ __forceinline__ void ldsm_x4(uint32_t& r0, uint32_t& r1,
                                        uint32_t& r2, uint32_t& r3, uint32_t a) {
    asm volatile("ldmatrix.sync.aligned.m8n8.x4.shared.b16 {%0,%1,%2,%3}, [%4];"
                 : "=r"(r0), "=r"(r1), "=r"(r2), "=r"(r3) : "r"(a));
}
__device__ __forceinline__ void cp16(uint32_t dst, const void* src) {
    asm volatile("cp.async.cg.shared.global [%0], [%1], 16;"
                 :: "r"(dst), "l"(src) : "memory");
}
__device__ __forceinline__ void cp_commit() {
    asm volatile("cp.async.commit_group;" ::: "memory");
}
__device__ __forceinline__ void cp_wait1() {
    asm volatile("cp.async.wait_group 1;" ::: "memory");
}
__device__ __forceinline__ void mma16816(float* c, const uint32_t* a, const uint32_t* b) {
    asm volatile(
        "mma.sync.aligned.m16n8k16.row.col.f32.f16.f16.f32 "
        "{%0,%1,%2,%3}, {%4,%5,%6,%7}, {%8,%9}, {%0,%1,%2,%3};"
        : "+f"(c[0]), "+f"(c[1]), "+f"(c[2]), "+f"(c[3])
        : "r"(a[0]), "r"(a[1]), "r"(a[2]), "r"(a[3]), "r"(b[0]), "r"(b[1]));
}

// ----------------------------- small kernels --------------------------------
__global__ void vq_init_kernel() {
    int t = blockIdx.x * blockDim.x + threadIdx.x;
    if (t < M_CODE) g_counts[t] = 0;
    if (t == 0) g_loss_sum = 0.0f;
}
__global__ void vq_e2_kernel(const float* __restrict__ embed) {
    int m = blockIdx.x * blockDim.x + threadIdx.x;
    if (m >= M_CODE) return;
    const float4* row = reinterpret_cast<const float4*>(embed + (size_t)m * D_DIM);
    float s = 0.0f;
#pragma unroll
    for (int i = 0; i < D_DIM / 4; i++) {
        float4 v = row[i];
        s += v.x * v.x + v.y * v.y + v.z * v.z + v.w * v.w;
    }
    g_e2[m] = s;
}
__global__ void vq_split_kernel(const float* __restrict__ embed) {
    int i = blockIdx.x * blockDim.x + threadIdx.x;   // one float4 each
    if (i >= M_CODE * D_DIM / 4) return;
    float4 v = reinterpret_cast<const float4*>(embed)[i];
    __half hx = __float2half_rn(v.x), hy = __float2half_rn(v.y);
    __half hz = __float2half_rn(v.z), hw = __float2half_rn(v.w);
    __half lx = __float2half_rn(v.x - __half2float(hx));
    __half ly = __float2half_rn(v.y - __half2float(hy));
    __half lz = __float2half_rn(v.z - __half2float(hz));
    __half lw = __float2half_rn(v.w - __half2float(hw));
    half2* ph = reinterpret_cast<half2*>(g_eh);
    half2* pl = reinterpret_cast<half2*>(g_el);
    ph[i * 2 + 0] = __halves2half2(hx, hy);
    ph[i * 2 + 1] = __halves2half2(hz, hw);
    pl[i * 2 + 0] = __halves2half2(lx, ly);
    pl[i * 2 + 1] = __halves2half2(lz, lw);
}

// ------------------------------ main kernel ---------------------------------
__global__ __launch_bounds__(256, 1)
void vq_main_kernel(const float* __restrict__ x,
                    const float* __restrict__ embed,
                    float* __restrict__ quant_out,
                    float* __restrict__ idx_out) {
    extern __shared__ char smem[];
    const uint32_t sb = smem_u32(smem);
    const int tid = threadIdx.x;
    const int lane = tid & 31;
    const int wid = tid >> 5;            // warp owns column stripe wid*16..+16
    const int row0 = blockIdx.x * 128;

    int* fidx = (int*)(smem + SM_FIDX);
    const uint32_t wB = sb + SM_B + wid * BW_WARP;

    // ldmatrix per-lane address offsets (bytes)
    //  A .x4: m0=rows0-7/k0-7, m1=rows8-15/k0-7, m2=rows0-7/k8-15, m3=rows8-15/k8-15
    const uint32_t aOff = ((uint32_t)(lane & 15) * A_PITCH + ((lane >> 4) & 1) * 8) * 2;
    //  B .x4: m0=n0-7/k0-7, m1=n0-7/k8-15, m2=n8-15/k0-7, m3=n8-15/k8-15
    const uint32_t bOff = (((uint32_t)(lane >> 4) * 8 + (lane & 7)) * B_PITCH +
                           ((lane >> 3) & 1) * 8) * 2;

    // per-lane cp.async role: lane&15 = code row within stripe, lane>>4 = split
    const int cpRow = lane & 15;
    const int cpSplit = lane >> 4;
    const __half* cpSrcBase = (cpSplit ? g_el : g_eh);
    const uint32_t cpDstBase = wB + cpSplit * BW_SPLIT + cpRow * (B_PITCH * 2);

    // ---- per-warp prologue: async-load own B slice for chunk 0 ----
    {
        const __half* src = cpSrcBase + (size_t)(wid * 16 + cpRow) * D_DIM;  // ct=0,kc=0
#pragma unroll
        for (int j = 0; j < 4; j++) cp16(cpDstBase + j * 16, src + j * 8);
        cp_commit();
    }

    // ---- stage x: split to fp16 hi/lo into smem [-2*x] ----
    for (int i = tid; i < 128 * 64; i += 256) {     // 8192 float4
        int row = i >> 6;
        int kq = (i & 63) << 2;
        float4 v = *(const float4*)(x + (size_t)(row0 + row) * D_DIM + kq);
        float ax = -2.0f * v.x, ay = -2.0f * v.y, az = -2.0f * v.z, aw = -2.0f * v.w;
        __half hx = __float2half_rn(ax), hy = __float2half_rn(ay);
        __half hz = __float2half_rn(az), hw = __float2half_rn(aw);
        __half lx = __float2half_rn(ax - __half2float(hx));
        __half ly = __float2half_rn(ay - __half2float(hy));
        __half lz = __float2half_rn(az - __half2float(hz));
        __half lw = __float2half_rn(aw - __half2float(hw));
        half2* dh = (half2*)(smem + SM_A + (size_t)(row * A_PITCH + kq) * 2);
        half2* dl = (half2*)(smem + SM_A + A_SPLIT + (size_t)(row * A_PITCH + kq) * 2);
        dh[0] = __halves2half2(hx, hy);
        dh[1] = __halves2half2(hz, hw);
        dl[0] = __halves2half2(lx, ly);
        dl[1] = __halves2half2(lz, lw);
    }
    __syncthreads();    // the ONLY pre-loop barrier: A tile visible to all warps

    float acc[8][2][4];
    float e2r[4];
    float bv[16];
    int bi[16];
#pragma unroll
    for (int s = 0; s < 16; s++) { bv[s] = 3.4e38f; bi[s] = 0; }

    // ======== barrier-free mainloop: warps fully decoupled ========
    for (int c = 0; c < CHUNKS; c++) {
        const int ct = c >> 3, kc = c & 7, buf = c & 1;

        // per-warp prefetch of chunk c+1 into own slice (other buffer)
        if (c + 1 < CHUNKS) {
            const int nct = (c + 1) >> 3, nkc = (c + 1) & 7, nbuf = (c + 1) & 1;
            const __half* src = cpSrcBase +
                (size_t)(nct * NT + wid * 16 + cpRow) * D_DIM + nkc * 32;
            uint32_t dst = cpDstBase + nbuf * BW_BUF;
#pragma unroll
            for (int j = 0; j < 4; j++) cp16(dst + j * 16, src + j * 8);
        }
        cp_commit();
        cp_wait1();        // chunk c's slice now resident (per-thread ordering)

        if (kc == 0) {
#pragma unroll
            for (int mt = 0; mt < 8; mt++)
#pragma unroll
                for (int nt = 0; nt < 2; nt++)
#pragma unroll
                    for (int q = 0; q < 4; q++) acc[mt][nt][q] = 0.0f;
#pragma unroll
            for (int nt = 0; nt < 2; nt++)
#pragma unroll
                for (int q = 0; q < 2; q++)
                    e2r[nt * 2 + q] =
                        __ldg(&g_e2[ct * NT + wid * 16 + nt * 8 + (lane & 3) * 2 + q]);
        }

        // ---- compute: 2 k-steps of 16 ----
#pragma unroll
        for (int ks = 0; ks < 2; ks++) {
            const uint32_t kk0 = (kc * 32 + ks * 16) * 2;   // A k byte offset
            const uint32_t kl0 = (ks * 16) * 2;             // B k byte offset

            // B fragments: [nt][split][reg], 1 ldmatrix.x4 per split
            uint32_t b[2][2][2];
#pragma unroll
            for (int s = 0; s < 2; s++) {
                uint32_t base = wB + buf * BW_BUF + s * BW_SPLIT + bOff + kl0;
                ldsm_x4(b[0][s][0], b[0][s][1], b[1][s][0], b[1][s][1], base);
            }

            uint32_t a[8][4];
            // --- a = A_hi; sweeps hh then hl (a reused) ---
            {
                uint32_t base = sb + SM_A + aOff + kk0;
#pragma unroll
                for (int mt = 0; mt < 8; mt++)
                    ldsm_x4(a[mt][0], a[mt][1], a[mt][2], a[mt][3],
                            base + mt * (16 * A_PITCH * 2));
            }
#pragma unroll
            for (int mt = 0; mt < 8; mt++)
#pragma unroll
                for (int nt = 0; nt < 2; nt++)
                    mma16816(acc[mt][nt], a[mt], b[nt][0]);
#pragma unroll
            for (int mt = 0; mt < 8; mt++)
#pragma unroll
                for (int nt = 0; nt < 2; nt++)
                    mma16816(acc[mt][nt], a[mt], b[nt][1]);
            // --- a = A_lo; sweep lh ---
            {
                uint32_t base = sb + SM_A + A_SPLIT + aOff + kk0;
#pragma unroll
                for (int mt = 0; mt < 8; mt++)
                    ldsm_x4(a[mt][0], a[mt][1], a[mt][2], a[mt][3],
                            base + mt * (16 * A_PITCH * 2));
            }
#pragma unroll
            for (int mt = 0; mt < 8; mt++)
#pragma unroll
                for (int nt = 0; nt < 2; nt++)
                    mma16816(acc[mt][nt], a[mt], b[nt][0]);
        }

        // ---- epilogue of this code tile: fold e2, running argmin ----
        if (kc == 7) {
#pragma unroll
            for (int mt = 0; mt < 8; mt++)
#pragma unroll
                for (int h = 0; h < 2; h++) {
                    int slot = mt * 2 + h;
#pragma unroll
                    for (int nt = 0; nt < 2; nt++)
#pragma unroll
                        for (int q = 0; q < 2; q++) {
                            float s = e2r[nt * 2 + q] + acc[mt][nt][h * 2 + q];
                            int col = ct * NT + wid * 16 + nt * 8 + (lane & 3) * 2 + q;
                            if (s < bv[slot]) { bv[slot] = s; bi[slot] = col; }
                        }
                }
        }
    }

    // ---- cross-thread argmin reduce (reuse B smem region) ----
    __syncthreads();
    float* redv = (float*)(smem + SM_B);
    int*   redi = (int*)(smem + SM_B + 16384);
#pragma unroll
    for (int slot = 0; slot < 16; slot++) {
        int row_local = (slot >> 1) * 16 + (slot & 1) * 8 + (lane >> 2);
        int j = wid * 4 + (lane & 3);
        redv[row_local * 32 + j] = bv[slot];
        redi[row_local * 32 + j] = bi[slot];
    }
    __syncthreads();

    if (tid < 128) {
        float bvv = 3.4e38f;
        int bii = M_CODE;
#pragma unroll
        for (int j = 0; j < 32; j++) {
            float v = redv[tid * 32 + j];
            int i = redi[tid * 32 + j];
            if (v < bvv || (v == bvv && i < bii)) { bvv = v; bii = i; }
        }
        fidx[tid] = bii;
        idx_out[row0 + tid] = (float)bii;
        atomicAdd(&g_counts[bii], 1);
    }
    __syncthreads();

    // ---- gather quantized rows + loss partial ----
    float lsum = 0.0f;
    for (int e = tid; e < 128 * D_DIM; e += 256) {
        int r = e >> 8, k = e & 255;
        float q = embed[(size_t)fidx[r] * D_DIM + k];
        float xv = x[(size_t)(row0 + r) * D_DIM + k];
        quant_out[(size_t)(row0 + r) * D_DIM + k] = q;
        float dd = q - xv;
        lsum += dd * dd;
    }
    float* lred = (float*)(smem + SM_B + 32768);
    lred[tid] = lsum;
    __syncthreads();
#pragma unroll
    for (int s = 128; s > 0; s >>= 1) {
        if (tid < s) lred[tid] += lred[tid + s];
        __syncthreads();
    }
    if (tid == 0) atomicAdd(&g_loss_sum, lred[0]);
}

// ------------------------------ finalize -------------------------------------
__global__ void vq_finalize_kernel(float* __restrict__ loss_out,
                                   float* __restrict__ perp_out) {
    __shared__ float hred[256];
    int tid = threadIdx.x;
    float h = 0.0f;
    for (int m = tid; m < M_CODE; m += 256) {
        float p = (float)g_counts[m] * (1.0f / (float)N_TOK);
        h += p * logf(p + 1e-10f);
    }
    hred[tid] = h;
    __syncthreads();
#pragma unroll
    for (int s = 128; s > 0; s >>= 1) {
        if (tid < s) hred[tid] += hred[tid + s];
        __syncthreads();
    }
    if (tid == 0) {
        *loss_out = 1.25f * g_loss_sum / (float)((size_t)N_TOK * D_DIM);
        *perp_out = expf(-hred[0]);
    }
}

// ------------------------------ launch ---------------------------------------
extern "C" void kernel_launch(void* const* d_in, const int* in_sizes, int n_in,
                              void* d_out, int out_size) {
    const float* x = (const float*)d_in[0];      // [N, D]
    const float* embed = (const float*)d_in[1];  // [M, D]

    float* out = (float*)d_out;
    float* quant = out;
    float* idxp  = out + (size_t)N_TOK * D_DIM;
    float* lossp = idxp + N_TOK;
    float* perpp = lossp + 1;

    cudaFuncSetAttribute(vq_main_kernel,
                         cudaFuncAttributeMaxDynamicSharedMemorySize, SMEM_TOTAL);

    vq_init_kernel<<<(M_CODE + 255) / 256, 256>>>();
    vq_e2_kernel<<<(M_CODE + 255) / 256, 256>>>(embed);
    vq_split_kernel<<<(M_CODE * D_DIM / 4 + 255) / 256, 256>>>(embed);
    vq_main_kernel<<<N_TOK / 128, 256, SMEM_TOTAL>>>(x, embed, quant, idxp);
    vq_finalize_kernel<<<1, 256>>>(lossp, perpp);
}